// round 6
// baseline (speedup 1.0000x reference)
#include <cuda_runtime.h>
#include <cuda_bf16.h>
#include <math.h>

#define BOX_LOSS_SCALE 10.0f

static const int THREADS = 256;
static const int BLOCKS  = 592;    // 148 SMs * 4 blocks/SM -> one wave, 64-reg budget

// Per-block partials: x = sum_nll, y = sum_masked_mse, z = sum_mask
__device__ float4 g_partials[BLOCKS];
__device__ unsigned int g_counter = 0;

__device__ __forceinline__ float warp_sum(float v) {
    #pragma unroll
    for (int o = 16; o > 0; o >>= 1)
        v += __shfl_down_sync(0xFFFFFFFFu, v, o);
    return v;
}

// Fast, sufficiently accurate row loss pieces.
// lse = max(l0,l1) + log(1 + exp(-|l0-l1|)) via MUFU EX2/LG2 (abs err ~1e-7).
__device__ __forceinline__ void row_loss(float l0, float l1, int tc,
                                         float p0, float p1, float p2, float p3,
                                         float t0, float t1, float t2, float t3,
                                         float& s_nll, float& s_box, float& s_msk)
{
    float mx  = fmaxf(l0, l1);
    float d   = fabsf(l0 - l1);
    float lse = mx + __logf(1.0f + __expf(-d));
    float chosen = (tc == 0) ? l0 : l1;
    s_nll += lse - chosen;

    float e0 = p0 - t0, e1 = p1 - t1, e2 = p2 - t2, e3 = p3 - t3;
    float mse = e0 * e0;
    mse = fmaf(e1, e1, mse);
    mse = fmaf(e2, e2, mse);
    mse = fmaf(e3, e3, mse);
    if (tc != 0) { s_box += 0.25f * mse; s_msk += 1.0f; }
}

__global__ __launch_bounds__(THREADS, 4)
void loss_fused_kernel(const float* __restrict__ pred,
                       const int*   __restrict__ tclass,
                       const float* __restrict__ tbox,
                       float* __restrict__ out,
                       int n)
{
    float s_nll = 0.0f, s_box = 0.0f, s_msk = 0.0f;

    const int nthreads = gridDim.x * blockDim.x;
    const int gtid = blockIdx.x * blockDim.x + threadIdx.x;
    const int npairs = n >> 1;

    // 2 rows per iteration: all-wide, fully coalesced, front-batched loads.
    for (int p = gtid; p < npairs; p += nthreads) {
        const float4* pp = reinterpret_cast<const float4*>(pred + 12ll * p);
        float4 A = pp[0];                         // r0: l0 l1 b0 b1
        float4 B = pp[1];                         // r0: b2 b3 | r1: l0 l1
        float4 C = pp[2];                         // r1: b0 b1 b2 b3
        int2   tc2 = reinterpret_cast<const int2*>(tclass)[p];
        const float4* tb = reinterpret_cast<const float4*>(tbox) + 2ll * p;
        float4 T0 = tb[0];
        float4 T1 = tb[1];

        row_loss(A.x, A.y, tc2.x, A.z, A.w, B.x, B.y,
                 T0.x, T0.y, T0.z, T0.w, s_nll, s_box, s_msk);
        row_loss(B.z, B.w, tc2.y, C.x, C.y, C.z, C.w,
                 T1.x, T1.y, T1.z, T1.w, s_nll, s_box, s_msk);
    }

    // odd-n tail (not hit for N=4194304, kept for generality)
    if ((n & 1) && gtid == 0) {
        int i = n - 1;
        const float* pr = pred + 6ll * i;
        const float* tb = tbox + 4ll * i;
        row_loss(pr[0], pr[1], tclass[i], pr[2], pr[3], pr[4], pr[5],
                 tb[0], tb[1], tb[2], tb[3], s_nll, s_box, s_msk);
    }

    // ---- block reduction ----
    __shared__ float sh[3][THREADS / 32];
    s_nll = warp_sum(s_nll);
    s_box = warp_sum(s_box);
    s_msk = warp_sum(s_msk);
    int lane = threadIdx.x & 31;
    int wid  = threadIdx.x >> 5;
    if (lane == 0) { sh[0][wid] = s_nll; sh[1][wid] = s_box; sh[2][wid] = s_msk; }
    __syncthreads();

    __shared__ bool is_last;
    if (threadIdx.x == 0) {
        const int nw = THREADS / 32;
        float v0 = 0.0f, v1 = 0.0f, v2 = 0.0f;
        #pragma unroll
        for (int w = 0; w < nw; w++) { v0 += sh[0][w]; v1 += sh[1][w]; v2 += sh[2][w]; }
        g_partials[blockIdx.x] = make_float4(v0, v1, v2, 0.0f);
        __threadfence();  // partial visible before signaling
        unsigned int prev = atomicAdd(&g_counter, 1u);
        is_last = (prev == gridDim.x - 1);
    }
    __syncthreads();

    // ---- last block folds all partials (deterministic order) ----
    if (is_last) {
        double d_nll = 0.0, d_box = 0.0, d_msk = 0.0;
        for (int i = threadIdx.x; i < BLOCKS; i += THREADS) {
            float4 pt = g_partials[i];
            d_nll += (double)pt.x;
            d_box += (double)pt.y;
            d_msk += (double)pt.z;
        }
        #pragma unroll
        for (int o = 16; o > 0; o >>= 1) {
            d_nll += __shfl_down_sync(0xFFFFFFFFu, d_nll, o);
            d_box += __shfl_down_sync(0xFFFFFFFFu, d_box, o);
            d_msk += __shfl_down_sync(0xFFFFFFFFu, d_msk, o);
        }
        __shared__ double dsh[3][THREADS / 32];
        if (lane == 0) { dsh[0][wid] = d_nll; dsh[1][wid] = d_box; dsh[2][wid] = d_msk; }
        __syncthreads();
        if (threadIdx.x == 0) {
            double t0 = 0.0, t1 = 0.0, t2 = 0.0;
            #pragma unroll
            for (int w = 0; w < THREADS / 32; w++) { t0 += dsh[0][w]; t1 += dsh[1][w]; t2 += dsh[2][w]; }
            double class_loss = t0 / (double)n;
            double box_count  = 1e-06 + t2;
            out[0] = (float)(class_loss + (double)BOX_LOSS_SCALE * t1 / box_count);
            g_counter = 0;  // reset for next graph replay
        }
    }
}

extern "C" void kernel_launch(void* const* d_in, const int* in_sizes, int n_in,
                              void* d_out, int out_size)
{
    const float* pred   = (const float*)d_in[0];
    const int*   tclass = (const int*)d_in[1];
    const float* tbox   = (const float*)d_in[2];
    float* out = (float*)d_out;

    int n = in_sizes[1];  // target_class element count = N

    loss_fused_kernel<<<BLOCKS, THREADS>>>(pred, tclass, tbox, out, n);
}

// round 7
// speedup vs baseline: 1.0060x; 1.0060x over previous
#include <cuda_runtime.h>
#include <cuda_bf16.h>
#include <math.h>

#define BOX_LOSS_SCALE 10.0f

static const int THREADS = 256;
static const int BLOCKS  = 592;    // 148 SMs * 4 blocks/SM -> one wave, 64-reg budget

// Per-block partials: x = sum_nll, y = sum_masked_mse, z = sum_mask
__device__ float4 g_partials[BLOCKS];
__device__ unsigned int g_counter = 0;

__device__ __forceinline__ float warp_sum(float v) {
    #pragma unroll
    for (int o = 16; o > 0; o >>= 1)
        v += __shfl_down_sync(0xFFFFFFFFu, v, o);
    return v;
}

// lse = max(l0,l1) + log(1 + exp(-|l0-l1|)) via MUFU EX2/LG2 (abs err ~1e-7).
__device__ __forceinline__ void row_loss(float l0, float l1, int tc,
                                         float p0, float p1, float p2, float p3,
                                         float t0, float t1, float t2, float t3,
                                         float& s_nll, float& s_box, float& s_msk)
{
    float mx  = fmaxf(l0, l1);
    float d   = fabsf(l0 - l1);
    float lse = mx + __logf(1.0f + __expf(-d));
    float chosen = (tc == 0) ? l0 : l1;
    s_nll += lse - chosen;

    float e0 = p0 - t0, e1 = p1 - t1, e2 = p2 - t2, e3 = p3 - t3;
    float mse = e0 * e0;
    mse = fmaf(e1, e1, mse);
    mse = fmaf(e2, e2, mse);
    mse = fmaf(e3, e3, mse);
    if (tc != 0) { s_box += 0.25f * mse; s_msk += 1.0f; }
}

__global__ __launch_bounds__(THREADS, 4)
void loss_fused_kernel(const float* __restrict__ pred,
                       const int*   __restrict__ tclass,
                       const float* __restrict__ tbox,
                       float* __restrict__ out,
                       int n)
{
    float s_nll = 0.0f, s_box = 0.0f, s_msk = 0.0f;

    const int nthreads = gridDim.x * blockDim.x;
    const int gtid = blockIdx.x * blockDim.x + threadIdx.x;
    const int nquads = n >> 2;   // 4 rows per iteration

    for (int q = gtid; q < nquads; q += nthreads) {
        // Front-batched wide loads: 6 + 4 + 1 = 11 LDG.128-class requests
        float4 F[6];                                     // 4 pred rows = 96B
        const float4* pp = reinterpret_cast<const float4*>(pred + 24ll * q);
        #pragma unroll
        for (int j = 0; j < 6; j++) F[j] = pp[j];

        float4 T[4];                                     // 4 tbox rows = 64B
        const float4* tb = reinterpret_cast<const float4*>(tbox) + 4ll * q;
        #pragma unroll
        for (int j = 0; j < 4; j++) T[j] = tb[j];

        int4 tc4 = reinterpret_cast<const int4*>(tclass)[q];

        const float* pf = reinterpret_cast<const float*>(F);
        const int tcs[4] = { tc4.x, tc4.y, tc4.z, tc4.w };
        #pragma unroll
        for (int r = 0; r < 4; r++) {
            row_loss(pf[6*r], pf[6*r+1], tcs[r],
                     pf[6*r+2], pf[6*r+3], pf[6*r+4], pf[6*r+5],
                     T[r].x, T[r].y, T[r].z, T[r].w,
                     s_nll, s_box, s_msk);
        }
    }

    // tail rows (n % 4) — not hit for N=4194304, kept for generality
    if (gtid == 0) {
        for (int i = n & ~3; i < n; i++) {
            const float* pr = pred + 6ll * i;
            const float* tb = tbox + 4ll * i;
            row_loss(pr[0], pr[1], tclass[i], pr[2], pr[3], pr[4], pr[5],
                     tb[0], tb[1], tb[2], tb[3], s_nll, s_box, s_msk);
        }
    }

    // ---- block reduction ----
    __shared__ float sh[3][THREADS / 32];
    s_nll = warp_sum(s_nll);
    s_box = warp_sum(s_box);
    s_msk = warp_sum(s_msk);
    int lane = threadIdx.x & 31;
    int wid  = threadIdx.x >> 5;
    if (lane == 0) { sh[0][wid] = s_nll; sh[1][wid] = s_box; sh[2][wid] = s_msk; }
    __syncthreads();

    __shared__ bool is_last;
    if (threadIdx.x == 0) {
        const int nw = THREADS / 32;
        float v0 = 0.0f, v1 = 0.0f, v2 = 0.0f;
        #pragma unroll
        for (int w = 0; w < nw; w++) { v0 += sh[0][w]; v1 += sh[1][w]; v2 += sh[2][w]; }
        g_partials[blockIdx.x] = make_float4(v0, v1, v2, 0.0f);
        __threadfence();  // partial visible before signaling
        unsigned int prev = atomicAdd(&g_counter, 1u);
        is_last = (prev == gridDim.x - 1);
    }
    __syncthreads();

    // ---- last block folds all partials (deterministic order) ----
    if (is_last) {
        double d_nll = 0.0, d_box = 0.0, d_msk = 0.0;
        for (int i = threadIdx.x; i < BLOCKS; i += THREADS) {
            float4 pt = g_partials[i];
            d_nll += (double)pt.x;
            d_box += (double)pt.y;
            d_msk += (double)pt.z;
        }
        #pragma unroll
        for (int o = 16; o > 0; o >>= 1) {
            d_nll += __shfl_down_sync(0xFFFFFFFFu, d_nll, o);
            d_box += __shfl_down_sync(0xFFFFFFFFu, d_box, o);
            d_msk += __shfl_down_sync(0xFFFFFFFFu, d_msk, o);
        }
        __shared__ double dsh[3][THREADS / 32];
        if (lane == 0) { dsh[0][wid] = d_nll; dsh[1][wid] = d_box; dsh[2][wid] = d_msk; }
        __syncthreads();
        if (threadIdx.x == 0) {
            double t0 = 0.0, t1 = 0.0, t2 = 0.0;
            #pragma unroll
            for (int w = 0; w < THREADS / 32; w++) { t0 += dsh[0][w]; t1 += dsh[1][w]; t2 += dsh[2][w]; }
            double class_loss = t0 / (double)n;
            double box_count  = 1e-06 + t2;
            out[0] = (float)(class_loss + (double)BOX_LOSS_SCALE * t1 / box_count);
            g_counter = 0;  // reset for next graph replay
        }
    }
}

extern "C" void kernel_launch(void* const* d_in, const int* in_sizes, int n_in,
                              void* d_out, int out_size)
{
    const float* pred   = (const float*)d_in[0];
    const int*   tclass = (const int*)d_in[1];
    const float* tbox   = (const float*)d_in[2];
    float* out = (float*)d_out;

    int n = in_sizes[1];  // target_class element count = N

    loss_fused_kernel<<<BLOCKS, THREADS>>>(pred, tclass, tbox, out, n);
}